// round 4
// baseline (speedup 1.0000x reference)
#include <cuda_runtime.h>
#include <math.h>

#define S_TXT 512
#define S_ALL 4608
#define DM    3072
#define NH    24
#define NKV   8
#define HD    128
#define KV_W  (NKV*HD)   /* 1024 */

// Scratch (static device globals: allocation-free per harness rules)
__device__ float g_Q[S_ALL * DM];     // [s][h][hd] joint, text rows first
__device__ float g_K[S_ALL * KV_W];
__device__ float g_V[S_ALL * KV_W];
__device__ float g_O[S_ALL * DM];

// ---------------------------------------------------------------------------
// GEMM: C[M,N] = A[M,K] @ W[K,N] + bias[N]     (row-major, all dims %128/%16)
// ---------------------------------------------------------------------------
__global__ __launch_bounds__(256, 2)
void gemm_bias_kernel(const float* __restrict__ A, const float* __restrict__ W,
                      const float* __restrict__ bias, float* __restrict__ C,
                      int M, int N, int K)
{
    __shared__ float As[16][128];   // [k][m]
    __shared__ float Bs[16][128];   // [k][n]
    const int tid = threadIdx.x;
    const int ty = tid >> 4, tx = tid & 15;
    const int bm = blockIdx.y * 128, bn = blockIdx.x * 128;
    const float* Ab = A + (size_t)bm * K;
    const float* Wb = W + bn;

    float acc[8][8];
#pragma unroll
    for (int i = 0; i < 8; i++)
#pragma unroll
        for (int j = 0; j < 8; j++) acc[i][j] = 0.f;

    for (int k0 = 0; k0 < K; k0 += 16) {
#pragma unroll
        for (int p = 0; p < 2; p++) {           // A tile: 128m x 16k (transpose)
            int slot = tid + p * 256;
            int m = slot >> 2, kg = slot & 3;
            float4 a = *(const float4*)(Ab + (size_t)m * K + k0 + kg * 4);
            As[kg*4+0][m] = a.x; As[kg*4+1][m] = a.y;
            As[kg*4+2][m] = a.z; As[kg*4+3][m] = a.w;
        }
#pragma unroll
        for (int p = 0; p < 2; p++) {           // B tile: 16k x 128n
            int slot = tid + p * 256;
            int kk = slot >> 5, n4 = slot & 31;
            *(float4*)&Bs[kk][n4*4] = *(const float4*)(Wb + (size_t)(k0+kk) * N + n4 * 4);
        }
        __syncthreads();
#pragma unroll
        for (int kk = 0; kk < 16; kk++) {
            float a[8], b[8];
            *(float4*)&a[0] = *(float4*)&As[kk][ty*8];
            *(float4*)&a[4] = *(float4*)&As[kk][ty*8+4];
            *(float4*)&b[0] = *(float4*)&Bs[kk][tx*8];
            *(float4*)&b[4] = *(float4*)&Bs[kk][tx*8+4];
#pragma unroll
            for (int i = 0; i < 8; i++)
#pragma unroll
                for (int j = 0; j < 8; j++)
                    acc[i][j] = fmaf(a[i], b[j], acc[i][j]);
        }
        __syncthreads();
    }

    float bb[8];
    *(float4*)&bb[0] = *(const float4*)(bias + bn + tx*8);
    *(float4*)&bb[4] = *(const float4*)(bias + bn + tx*8 + 4);
#pragma unroll
    for (int i = 0; i < 8; i++) {
        float* cp = C + (size_t)(bm + ty*8 + i) * N + bn + tx*8;
        *(float4*)(cp)     = make_float4(acc[i][0]+bb[0], acc[i][1]+bb[1],
                                         acc[i][2]+bb[2], acc[i][3]+bb[3]);
        *(float4*)(cp + 4) = make_float4(acc[i][4]+bb[4], acc[i][5]+bb[5],
                                         acc[i][6]+bb[6], acc[i][7]+bb[7]);
    }
}

// ---------------------------------------------------------------------------
// Fused RMSNorm (eps=1e-6) + RoPE + optional scale. One warp per (s, head).
// ---------------------------------------------------------------------------
__global__ void normrope_kernel(float* __restrict__ buf, int nheads,
                                const float* __restrict__ w_img,
                                const float* __restrict__ w_txt,
                                const float* __restrict__ rope, float scale)
{
    int gw = (blockIdx.x * blockDim.x + threadIdx.x) >> 5;
    int lane = threadIdx.x & 31;
    if (gw >= S_ALL * nheads) return;
    int s = gw / nheads, h = gw - s * nheads;
    float* row = buf + (size_t)s * (nheads * HD) + h * HD + lane * 4;
    float4 x = *(float4*)row;
    float ss = x.x*x.x + x.y*x.y + x.z*x.z + x.w*x.w;
#pragma unroll
    for (int m = 16; m >= 1; m >>= 1) ss += __shfl_xor_sync(0xffffffffu, ss, m);
    float r = rsqrtf(ss * (1.0f / HD) + 1e-6f);
    const float* w = (s < S_TXT ? w_txt : w_img) + lane * 4;
    float4 wv = *(const float4*)w;
    float x0 = x.x*r*wv.x, x1 = x.y*r*wv.y, x2 = x.z*r*wv.z, x3 = x.w*r*wv.w;
    const float* cp = rope + (size_t)s * HD + lane * 4;
    const float* sp = cp + (size_t)S_ALL * HD;
    float4 c  = *(const float4*)cp;
    float4 sn = *(const float4*)sp;
    float4 y;
    y.x = (x0*c.x - x1*sn.x) * scale;
    y.y = (x1*c.y + x0*sn.y) * scale;
    y.z = (x2*c.z - x3*sn.z) * scale;
    y.w = (x3*c.w + x2*sn.w) * scale;
    *(float4*)row = y;
}

// ---------------------------------------------------------------------------
// Flash attention, fp32 online softmax, 64x64 tiles, GQA kv head = h/3.
// ---------------------------------------------------------------------------
#define FL_SMEM ((128*64 + 128*64 + 64*132 + 64*68) * 4)

__global__ __launch_bounds__(256)
void flash_kernel(const float* __restrict__ Qg, const float* __restrict__ Kg,
                  const float* __restrict__ Vg, float* __restrict__ Og)
{
    extern __shared__ float sm[];
    float* Qs = sm;                  // [128][64]
    float* Ks = Qs + 128 * 64;       // [128][64]
    float* Vs = Ks + 128 * 64;       // [64][132]
    float* Ps = Vs + 64 * 132;       // [64][68]
    const int tid = threadIdx.x;
    const int ty = tid >> 4, tx = tid & 15;
    const int h  = blockIdx.y;
    const int q0 = blockIdx.x * 64;
    const int hk = h / (NH / NKV);

    {   // load Q tile (transposed)
        int m = tid >> 2, kg = tid & 3;
        const float* qp = Qg + (size_t)(q0 + m) * DM + h * HD;
#pragma unroll
        for (int p = 0; p < 8; p++) {
            int d = p * 16 + kg * 4;
            float4 a = *(const float4*)(qp + d);
            Qs[(d+0)*64+m] = a.x; Qs[(d+1)*64+m] = a.y;
            Qs[(d+2)*64+m] = a.z; Qs[(d+3)*64+m] = a.w;
        }
    }

    float mrow[4], lrow[4], o[4][8];
#pragma unroll
    for (int i = 0; i < 4; i++) {
        mrow[i] = -1e30f; lrow[i] = 0.f;
#pragma unroll
        for (int c = 0; c < 8; c++) o[i][c] = 0.f;
    }

    for (int kt = 0; kt < S_ALL / 64; kt++) {
        __syncthreads();
        {   // load K,V tiles
            int n = tid >> 2, kg = tid & 3;
            const float* kp = Kg + (size_t)(kt * 64 + n) * KV_W + hk * HD;
            const float* vp = Vg + (size_t)(kt * 64 + n) * KV_W + hk * HD;
#pragma unroll
            for (int p = 0; p < 8; p++) {
                int d = p * 16 + kg * 4;
                float4 a = *(const float4*)(kp + d);
                float4 v = *(const float4*)(vp + d);
                Ks[(d+0)*64+n] = a.x; Ks[(d+1)*64+n] = a.y;
                Ks[(d+2)*64+n] = a.z; Ks[(d+3)*64+n] = a.w;
                *(float4*)&Vs[n * 132 + d] = v;
            }
        }
        __syncthreads();

        float sacc[4][4];
#pragma unroll
        for (int i = 0; i < 4; i++)
#pragma unroll
            for (int j = 0; j < 4; j++) sacc[i][j] = 0.f;
#pragma unroll 8
        for (int d = 0; d < 128; d++) {
            float4 a = *(float4*)&Qs[d * 64 + ty * 4];
            float4 b = *(float4*)&Ks[d * 64 + tx * 4];
            sacc[0][0]=fmaf(a.x,b.x,sacc[0][0]); sacc[0][1]=fmaf(a.x,b.y,sacc[0][1]);
            sacc[0][2]=fmaf(a.x,b.z,sacc[0][2]); sacc[0][3]=fmaf(a.x,b.w,sacc[0][3]);
            sacc[1][0]=fmaf(a.y,b.x,sacc[1][0]); sacc[1][1]=fmaf(a.y,b.y,sacc[1][1]);
            sacc[1][2]=fmaf(a.y,b.z,sacc[1][2]); sacc[1][3]=fmaf(a.y,b.w,sacc[1][3]);
            sacc[2][0]=fmaf(a.z,b.x,sacc[2][0]); sacc[2][1]=fmaf(a.z,b.y,sacc[2][1]);
            sacc[2][2]=fmaf(a.z,b.z,sacc[2][2]); sacc[2][3]=fmaf(a.z,b.w,sacc[2][3]);
            sacc[3][0]=fmaf(a.w,b.x,sacc[3][0]); sacc[3][1]=fmaf(a.w,b.y,sacc[3][1]);
            sacc[3][2]=fmaf(a.w,b.z,sacc[3][2]); sacc[3][3]=fmaf(a.w,b.w,sacc[3][3]);
        }

#pragma unroll
        for (int i = 0; i < 4; i++) {
            float mx = fmaxf(fmaxf(sacc[i][0], sacc[i][1]),
                             fmaxf(sacc[i][2], sacc[i][3]));
#pragma unroll
            for (int msk = 8; msk >= 1; msk >>= 1)
                mx = fmaxf(mx, __shfl_xor_sync(0xffffffffu, mx, msk));
            float mn   = fmaxf(mrow[i], mx);
            float corr = __expf(mrow[i] - mn);
            mrow[i] = mn;
            float p0 = __expf(sacc[i][0] - mn);
            float p1 = __expf(sacc[i][1] - mn);
            float p2 = __expf(sacc[i][2] - mn);
            float p3 = __expf(sacc[i][3] - mn);
            float rs = p0 + p1 + p2 + p3;
#pragma unroll
            for (int msk = 8; msk >= 1; msk >>= 1)
                rs += __shfl_xor_sync(0xffffffffu, rs, msk);
            lrow[i] = lrow[i] * corr + rs;
#pragma unroll
            for (int c = 0; c < 8; c++) o[i][c] *= corr;
            *(float4*)&Ps[(ty*4 + i) * 68 + tx*4] = make_float4(p0, p1, p2, p3);
        }
        __syncthreads();

#pragma unroll 4
        for (int n = 0; n < 64; n++) {
            float4 b0 = *(float4*)&Vs[n * 132 + tx * 4];
            float4 b1 = *(float4*)&Vs[n * 132 + 64 + tx * 4];
#pragma unroll
            for (int i = 0; i < 4; i++) {
                float av = Ps[(ty*4 + i) * 68 + n];
                o[i][0]=fmaf(av,b0.x,o[i][0]); o[i][1]=fmaf(av,b0.y,o[i][1]);
                o[i][2]=fmaf(av,b0.z,o[i][2]); o[i][3]=fmaf(av,b0.w,o[i][3]);
                o[i][4]=fmaf(av,b1.x,o[i][4]); o[i][5]=fmaf(av,b1.y,o[i][5]);
                o[i][6]=fmaf(av,b1.z,o[i][6]); o[i][7]=fmaf(av,b1.w,o[i][7]);
            }
        }
    }

#pragma unroll
    for (int i = 0; i < 4; i++) {
        float inv = 1.0f / lrow[i];
        float* op = Og + (size_t)(q0 + ty*4 + i) * DM + h * HD;
        *(float4*)(op + tx*4)      = make_float4(o[i][0]*inv, o[i][1]*inv,
                                                 o[i][2]*inv, o[i][3]*inv);
        *(float4*)(op + 64 + tx*4) = make_float4(o[i][4]*inv, o[i][5]*inv,
                                                 o[i][6]*inv, o[i][7]*inv);
    }
}

// ---------------------------------------------------------------------------
extern "C" void kernel_launch(void* const* d_in, const int* in_sizes, int n_in,
                              void* d_out, int out_size)
{
    const float* hidden  = (const float*)d_in[0];
    const float* encoder = (const float*)d_in[1];
    const float* rope    = (const float*)d_in[2];
    const float* Wq  = (const float*)d_in[3];  const float* bq  = (const float*)d_in[4];
    const float* Wk  = (const float*)d_in[5];  const float* bk  = (const float*)d_in[6];
    const float* Wv  = (const float*)d_in[7];  const float* bv  = (const float*)d_in[8];
    const float* aWq = (const float*)d_in[9];  const float* abq = (const float*)d_in[10];
    const float* aWk = (const float*)d_in[11]; const float* abk = (const float*)d_in[12];
    const float* aWv = (const float*)d_in[13]; const float* abv = (const float*)d_in[14];
    const float* nq  = (const float*)d_in[15]; const float* nk  = (const float*)d_in[16];
    const float* anq = (const float*)d_in[17]; const float* ank = (const float*)d_in[18];
    const float* Wout  = (const float*)d_in[19]; const float* bout  = (const float*)d_in[20];
    const float* Waout = (const float*)d_in[21]; const float* baout = (const float*)d_in[22];
    float* out = (float*)d_out;

    float *Qb, *Kb, *Vb, *Ob;
    cudaGetSymbolAddress((void**)&Qb, g_Q);
    cudaGetSymbolAddress((void**)&Kb, g_K);
    cudaGetSymbolAddress((void**)&Vb, g_V);
    cudaGetSymbolAddress((void**)&Ob, g_O);

    dim3 blk(256);

    // QKV projections (image rows at offset S_TXT, text rows at 0)
    gemm_bias_kernel<<<dim3(DM/128,   32), blk>>>(hidden,  Wq,  bq,  Qb + (size_t)S_TXT*DM,   4096, DM,   DM);
    gemm_bias_kernel<<<dim3(DM/128,   4),  blk>>>(encoder, aWq, abq, Qb,                      512,  DM,   DM);
    gemm_bias_kernel<<<dim3(KV_W/128, 32), blk>>>(hidden,  Wk,  bk,  Kb + (size_t)S_TXT*KV_W, 4096, KV_W, DM);
    gemm_bias_kernel<<<dim3(KV_W/128, 4),  blk>>>(encoder, aWk, abk, Kb,                      512,  KV_W, DM);
    gemm_bias_kernel<<<dim3(KV_W/128, 32), blk>>>(hidden,  Wv,  bv,  Vb + (size_t)S_TXT*KV_W, 4096, KV_W, DM);
    gemm_bias_kernel<<<dim3(KV_W/128, 4),  blk>>>(encoder, aWv, abv, Vb,                      512,  KV_W, DM);

    // RMSNorm + RoPE (Q also absorbs 1/sqrt(HD) score scale)
    normrope_kernel<<<(S_ALL*NH)/8,  256>>>(Qb, NH,  nq, anq, rope, 0.08838834764831845f);
    normrope_kernel<<<(S_ALL*NKV)/8, 256>>>(Kb, NKV, nk, ank, rope, 1.0f);

    // Flash attention
    cudaFuncSetAttribute(flash_kernel, cudaFuncAttributeMaxDynamicSharedMemorySize, FL_SMEM);
    flash_kernel<<<dim3(S_ALL/64, NH), blk, FL_SMEM>>>(Qb, Kb, Vb, Ob);

    // hid = O[512:] @ Wout + bout ; enc = O[:512] @ Waout + baout
    gemm_bias_kernel<<<dim3(DM/128, 32), blk>>>(Ob + (size_t)S_TXT*DM, Wout,  bout,  out,                   4096, DM, DM);
    gemm_bias_kernel<<<dim3(DM/128, 4),  blk>>>(Ob,                    Waout, baout, out + (size_t)4096*DM, 512,  DM, DM);
}

// round 14
// speedup vs baseline: 2.7752x; 2.7752x over previous
#include <cuda_runtime.h>
#include <cuda_bf16.h>
#include <math.h>
#include <stdint.h>

#define S_TXT 512
#define S_ALL 4608
#define DM    3072
#define NH    24
#define NKV   8
#define HD    128
#define KV_W  1024

// ---------------- scratch (device globals; allocation-free) ----------------
__device__ float g_Q[S_ALL * DM];
__device__ float g_K[S_ALL * KV_W];
__device__ float g_V[S_ALL * KV_W];

__device__ __nv_bfloat16 g_hid_h[4096*DM], g_hid_l[4096*DM];
__device__ __nv_bfloat16 g_enc_h[S_TXT*DM], g_enc_l[S_TXT*DM];
__device__ __nv_bfloat16 g_Qh[S_ALL*DM],  g_Ql[S_ALL*DM];
__device__ __nv_bfloat16 g_Kh[S_ALL*KV_W], g_Kl[S_ALL*KV_W];
__device__ __nv_bfloat16 g_Vh[S_ALL*KV_W], g_Vl[S_ALL*KV_W];
__device__ __nv_bfloat16 g_Oh[S_ALL*DM],  g_Ol[S_ALL*DM];

__device__ __nv_bfloat16 g_WqT_h [DM*DM],   g_WqT_l [DM*DM];
__device__ __nv_bfloat16 g_WkT_h [KV_W*DM], g_WkT_l [KV_W*DM];
__device__ __nv_bfloat16 g_WvT_h [KV_W*DM], g_WvT_l [KV_W*DM];
__device__ __nv_bfloat16 g_aWqT_h[DM*DM],   g_aWqT_l[DM*DM];
__device__ __nv_bfloat16 g_aWkT_h[KV_W*DM], g_aWkT_l[KV_W*DM];
__device__ __nv_bfloat16 g_aWvT_h[KV_W*DM], g_aWvT_l[KV_W*DM];
__device__ __nv_bfloat16 g_WoT_h [DM*DM],   g_WoT_l [DM*DM];
__device__ __nv_bfloat16 g_WaoT_h[DM*DM],   g_WaoT_l[DM*DM];

// ---------------- helpers ----------------
__device__ __forceinline__ uint32_t smem_u32(const void* p) {
    uint32_t a;
    asm("{ .reg .u64 t; cvta.to.shared.u64 t, %1; cvt.u32.u64 %0, t; }" : "=r"(a) : "l"(p));
    return a;
}
__device__ __forceinline__ void ldsm4(uint32_t* r, uint32_t a) {
    asm volatile("ldmatrix.sync.aligned.m8n8.x4.shared.b16 {%0,%1,%2,%3}, [%4];"
        : "=r"(r[0]), "=r"(r[1]), "=r"(r[2]), "=r"(r[3]) : "r"(a));
}
__device__ __forceinline__ void ldsm4t(uint32_t* r, uint32_t a) {
    asm volatile("ldmatrix.sync.aligned.m8n8.x4.trans.shared.b16 {%0,%1,%2,%3}, [%4];"
        : "=r"(r[0]), "=r"(r[1]), "=r"(r[2]), "=r"(r[3]) : "r"(a));
}
__device__ __forceinline__ void mmabf(float* c, const uint32_t* a, const uint32_t* b) {
    asm volatile("mma.sync.aligned.m16n8k16.row.col.f32.bf16.bf16.f32 "
        "{%0,%1,%2,%3}, {%4,%5,%6,%7}, {%8,%9}, {%0,%1,%2,%3};"
        : "+f"(c[0]), "+f"(c[1]), "+f"(c[2]), "+f"(c[3])
        : "r"(a[0]), "r"(a[1]), "r"(a[2]), "r"(a[3]), "r"(b[0]), "r"(b[1]));
}
__device__ __forceinline__ void cp16(uint32_t d, const void* s) {
    asm volatile("cp.async.cg.shared.global [%0], [%1], 16;" :: "r"(d), "l"(s));
}
#define CP_COMMIT() asm volatile("cp.async.commit_group;" ::: "memory")
#define CP_WAIT0()  asm volatile("cp.async.wait_group 0;" ::: "memory")
#define CP_WAIT1()  asm volatile("cp.async.wait_group 1;" ::: "memory")

__device__ __forceinline__ uint32_t pack2(float lo, float hi) {
    __nv_bfloat162 v = __floats2bfloat162_rn(lo, hi);
    return *reinterpret_cast<uint32_t*>(&v);
}
// fast e^x for x <= 0 via FMA pipe (degree-6 2^f poly); rel err ~1e-7
__device__ __forceinline__ float fexp(float x) {
    x = fmaxf(x, -80.f);
    float t = x * 1.4426950408889634f;
    float z = t + 12582912.f;
    int   ri = __float_as_int(z) - 0x4B400000;
    float r  = z - 12582912.f;
    float f  = t - r;
    float p  =             1.5403530e-4f;
    p = fmaf(p, f, 1.3333558e-3f);
    p = fmaf(p, f, 9.6181291e-3f);
    p = fmaf(p, f, 5.5504109e-2f);
    p = fmaf(p, f, 2.4022651e-1f);
    p = fmaf(p, f, 6.9314718e-1f);
    p = fmaf(p, f, 1.0f);
    return p * __int_as_float((ri + 127) << 23);
}

// ---------------------------------------------------------------------------
// fp32 -> bf16 hi/lo split (elementwise)
// ---------------------------------------------------------------------------
__global__ void split_kernel(const float* __restrict__ in,
                             __nv_bfloat16* __restrict__ oh,
                             __nv_bfloat16* __restrict__ ol, int n4)
{
    int i = blockIdx.x * blockDim.x + threadIdx.x;
    if (i >= n4) return;
    float4 v = ((const float4*)in)[i];
    __nv_bfloat162 h0 = __floats2bfloat162_rn(v.x, v.y);
    __nv_bfloat162 h1 = __floats2bfloat162_rn(v.z, v.w);
    __nv_bfloat162 l0 = __floats2bfloat162_rn(v.x - __bfloat162float(h0.x), v.y - __bfloat162float(h0.y));
    __nv_bfloat162 l1 = __floats2bfloat162_rn(v.z - __bfloat162float(h1.x), v.w - __bfloat162float(h1.y));
    ((__nv_bfloat162*)oh)[2*i]   = h0; ((__nv_bfloat162*)oh)[2*i+1] = h1;
    ((__nv_bfloat162*)ol)[2*i]   = l0; ((__nv_bfloat162*)ol)[2*i+1] = l1;
}

// ---------------------------------------------------------------------------
// weight transpose + split: in [K,N] fp32 -> out [N,K] bf16 hi/lo
// ---------------------------------------------------------------------------
__global__ void transpose_split_kernel(const float* __restrict__ in,
                                       __nv_bfloat16* __restrict__ oh,
                                       __nv_bfloat16* __restrict__ ol,
                                       int K, int N)
{
    __shared__ float t[32][33];
    int bx = blockIdx.x * 32, by = blockIdx.y * 32;
    int tx = threadIdx.x, ty = threadIdx.y;
#pragma unroll
    for (int i = 0; i < 4; i++)
        t[ty + 8*i][tx] = in[(size_t)(by + ty + 8*i) * N + bx + tx];
    __syncthreads();
#pragma unroll
    for (int i = 0; i < 4; i++) {
        float v = t[tx][ty + 8*i];
        int n = bx + ty + 8*i, k = by + tx;
        __nv_bfloat16 h = __float2bfloat16(v);
        __nv_bfloat16 l = __float2bfloat16(v - __bfloat162float(h));
        oh[(size_t)n * K + k] = h;
        ol[(size_t)n * K + k] = l;
    }
}

// ---------------------------------------------------------------------------
// mma.sync GEMM: C[M,N] = A[M,K] @ B[N,K]^T + bias, 3-term bf16 split.
// CTA 128x128, kc=32, 8 warps (32x64), 2-stage cp.async pipeline.
// smem rows: 40 elems (80B = 5x16B) -> conflict-free ldmatrix.
// ---------------------------------------------------------------------------
#define GMATB (128*40*2)      /* 10240 B per matrix */
#define GSTAGE (4*GMATB)      /* 40960 */
#define GSMEM  (2*GSTAGE)     /* 81920 */

__global__ __launch_bounds__(256, 1)
void tgemm_kernel(const __nv_bfloat16* __restrict__ Ah, const __nv_bfloat16* __restrict__ Al,
                  const __nv_bfloat16* __restrict__ Bh, const __nv_bfloat16* __restrict__ Bl,
                  const float* __restrict__ bias, float* __restrict__ C,
                  int N, int K)
{
    extern __shared__ char smem[];
    const uint32_t sb = smem_u32(smem);
    const int tid = threadIdx.x, lane = tid & 31, wid = tid >> 5;
    const int m0 = (wid >> 1) * 32, n0 = (wid & 1) * 64;
    const int bm = blockIdx.y * 128, bn = blockIdx.x * 128;

    const int pr = tid >> 1, pg = (tid & 1) * 2;          // prefetch: row, k-group base
    const __nv_bfloat16* pAh = Ah + (size_t)(bm + pr) * K + pg * 8;
    const __nv_bfloat16* pAl = Al + (size_t)(bm + pr) * K + pg * 8;
    const __nv_bfloat16* pBh = Bh + (size_t)(bn + pr) * K + pg * 8;
    const __nv_bfloat16* pBl = Bl + (size_t)(bn + pr) * K + pg * 8;
    const uint32_t pd = pr * 80 + pg * 16;

    auto prefetch = [&](int c, int s) {
        uint32_t st = sb + s * GSTAGE + pd;
        int k0 = c * 32;
        cp16(st,               pAh + k0); cp16(st + 16,               pAh + k0 + 8);
        cp16(st +   GMATB,     pAl + k0); cp16(st +   GMATB + 16,     pAl + k0 + 8);
        cp16(st + 2*GMATB,     pBh + k0); cp16(st + 2*GMATB + 16,     pBh + k0 + 8);
        cp16(st + 3*GMATB,     pBl + k0); cp16(st + 3*GMATB + 16,     pBl + k0 + 8);
    };

    float acc[2][8][4];
#pragma unroll
    for (int i = 0; i < 2; i++)
#pragma unroll
        for (int j = 0; j < 8; j++)
#pragma unroll
            for (int q = 0; q < 4; q++) acc[i][j][q] = 0.f;

    const int NCH = K / 32;
    prefetch(0, 0); CP_COMMIT();

    for (int c = 0; c < NCH; c++) {
        if (c + 1 < NCH) { prefetch(c + 1, (c + 1) & 1); CP_COMMIT(); CP_WAIT1(); }
        else             { CP_WAIT0(); }
        __syncthreads();
        const uint32_t st = sb + (c & 1) * GSTAGE;
#pragma unroll
        for (int ks = 0; ks < 2; ks++) {
            uint32_t ah[2][4], al[2][4];
#pragma unroll
            for (int i = 0; i < 2; i++) {
                uint32_t qa = (m0 + 16*i + (lane & 15)) * 80 + ks*32 + (lane >> 4) * 16;
                ldsm4(ah[i], st + qa);
                ldsm4(al[i], st + GMATB + qa);
            }
#pragma unroll
            for (int p = 0; p < 4; p++) {
                uint32_t ro = (n0 + 16*p + (lane & 7) + (((lane >> 3) > 1) ? 8 : 0)) * 80
                            + ks*32 + ((lane >> 3) & 1) * 16;
                uint32_t bh4[4], bl4[4];
                ldsm4(bh4, st + 2*GMATB + ro);
                ldsm4(bl4, st + 3*GMATB + ro);
#pragma unroll
                for (int i = 0; i < 2; i++) {
                    mmabf(acc[i][2*p],   ah[i], bh4);
                    mmabf(acc[i][2*p+1], ah[i], bh4 + 2);
                    mmabf(acc[i][2*p],   ah[i], bl4);
                    mmabf(acc[i][2*p+1], ah[i], bl4 + 2);
                    mmabf(acc[i][2*p],   al[i], bh4);
                    mmabf(acc[i][2*p+1], al[i], bh4 + 2);
                }
            }
        }
        __syncthreads();
    }

#pragma unroll
    for (int i = 0; i < 2; i++)
#pragma unroll
        for (int j = 0; j < 8; j++) {
            int row = bm + m0 + 16*i + (lane >> 2);
            int col = bn + n0 + 8*j + (lane & 3) * 2;
            float2 b2 = *(const float2*)(bias + col);
            *(float2*)(C + (size_t)row * N + col) =
                make_float2(acc[i][j][0] + b2.x, acc[i][j][1] + b2.y);
            *(float2*)(C + (size_t)(row + 8) * N + col) =
                make_float2(acc[i][j][2] + b2.x, acc[i][j][3] + b2.y);
        }
}

// ---------------------------------------------------------------------------
// RMSNorm + RoPE + scale, writing bf16 hi/lo. One warp per (s, head).
// ---------------------------------------------------------------------------
__global__ void normrope_split_kernel(const float* __restrict__ in, int nheads,
                                      const float* __restrict__ w_img,
                                      const float* __restrict__ w_txt,
                                      const float* __restrict__ rope, float scale,
                                      __nv_bfloat16* __restrict__ oh,
                                      __nv_bfloat16* __restrict__ ol)
{
    int gw = (blockIdx.x * blockDim.x + threadIdx.x) >> 5;
    int lane = threadIdx.x & 31;
    if (gw >= S_ALL * nheads) return;
    int s = gw / nheads, h = gw - s * nheads;
    const float* row = in + (size_t)s * (nheads * HD) + h * HD + lane * 4;
    float4 x = *(const float4*)row;
    float ss = x.x*x.x + x.y*x.y + x.z*x.z + x.w*x.w;
#pragma unroll
    for (int m = 16; m >= 1; m >>= 1) ss += __shfl_xor_sync(0xffffffffu, ss, m);
    float r = rsqrtf(ss * (1.0f / HD) + 1e-6f);
    const float* w = (s < S_TXT ? w_txt : w_img) + lane * 4;
    float4 wv = *(const float4*)w;
    float x0 = x.x*r*wv.x, x1 = x.y*r*wv.y, x2 = x.z*r*wv.z, x3 = x.w*r*wv.w;
    const float* cp = rope + (size_t)s * HD + lane * 4;
    const float* sp = cp + (size_t)S_ALL * HD;
    float4 c  = *(const float4*)cp;
    float4 sn = *(const float4*)sp;
    float y0 = (x0*c.x - x1*sn.x) * scale;
    float y1 = (x1*c.y + x0*sn.y) * scale;
    float y2 = (x2*c.z - x3*sn.z) * scale;
    float y3 = (x3*c.w + x2*sn.w) * scale;
    size_t idx = (size_t)s * (nheads * HD) + h * HD + lane * 4;
    __nv_bfloat162 h0 = __floats2bfloat162_rn(y0, y1);
    __nv_bfloat162 h1 = __floats2bfloat162_rn(y2, y3);
    __nv_bfloat162 l0 = __floats2bfloat162_rn(y0 - __bfloat162float(h0.x), y1 - __bfloat162float(h0.y));
    __nv_bfloat162 l1 = __floats2bfloat162_rn(y2 - __bfloat162float(h1.x), y3 - __bfloat162float(h1.y));
    ((__nv_bfloat162*)(oh + idx))[0] = h0; ((__nv_bfloat162*)(oh + idx))[1] = h1;
    ((__nv_bfloat162*)(ol + idx))[0] = l0; ((__nv_bfloat162*)(ol + idx))[1] = l1;
}

// ---------------------------------------------------------------------------
// Flash attention via mma.sync, 3-term hi/lo split for QK^T and PV.
// CTA: 128 Q rows, 8 warps x 16 rows (full-width). K/V tiles 64 seq,
// 2-stage cp.async. GQA kv head = h/3. Scale pre-folded into Q.
// ---------------------------------------------------------------------------
#define FSTR  136                      /* smem row stride, elems (272B = 17x16B) */
#define FQMAT (128*FSTR*2)             /* 34816 */
#define FKMAT (64*FSTR*2)              /* 17408 */
#define FSTG  (4*FKMAT)                /* 69632 */
#define F_SMEM (2*FQMAT + 2*FSTG)      /* 208896 */

__global__ __launch_bounds__(256, 1)
void flashmma_kernel(const __nv_bfloat16* __restrict__ Qh, const __nv_bfloat16* __restrict__ Ql,
                     const __nv_bfloat16* __restrict__ Kh, const __nv_bfloat16* __restrict__ Kl,
                     const __nv_bfloat16* __restrict__ Vh, const __nv_bfloat16* __restrict__ Vl,
                     __nv_bfloat16* __restrict__ Oh, __nv_bfloat16* __restrict__ Ol)
{
    extern __shared__ char smem[];
    const uint32_t sb = smem_u32(smem);
    const int tid = threadIdx.x, lane = tid & 31, wid = tid >> 5;
    const int h = blockIdx.y, q0 = blockIdx.x * 128;
    const int hk = h / 3;
    const uint32_t sQh = sb, sQl = sb + FQMAT, sKV = sb + 2*FQMAT;

    {   // Q tile prefetch (group 0, with KV tile 0)
        int r = tid >> 1, cg0 = (tid & 1) * 8;
        const __nv_bfloat16* sh = Qh + (size_t)(q0 + r) * DM + h * HD + cg0 * 8;
        const __nv_bfloat16* sl = Ql + (size_t)(q0 + r) * DM + h * HD + cg0 * 8;
        uint32_t d = r * 272 + cg0 * 16;
#pragma unroll
        for (int j = 0; j < 8; j++) {
            cp16(sQh + d + j*16, sh + j*8);
            cp16(sQl + d + j*16, sl + j*8);
        }
    }
    const int kr = tid >> 2, kc0 = (tid & 3) * 4;
    auto pref_kv = [&](int kt, int s) {
        uint32_t st = sKV + s * FSTG + kr * 272 + kc0 * 16;
        size_t g = (size_t)(kt * 64 + kr) * KV_W + hk * HD + kc0 * 8;
#pragma unroll
        for (int j = 0; j < 4; j++) {
            cp16(st +           j*16, Kh + g + j*8);
            cp16(st +   FKMAT + j*16, Kl + g + j*8);
            cp16(st + 2*FKMAT + j*16, Vh + g + j*8);
            cp16(st + 3*FKMAT + j*16, Vl + g + j*8);
        }
    };
    pref_kv(0, 0); CP_COMMIT();

    float oacc[16][4];
#pragma unroll
    for (int j = 0; j < 16; j++)
#pragma unroll
        for (int q = 0; q < 4; q++) oacc[j][q] = 0.f;
    float mrow0 = -1e30f, mrow1 = -1e30f, lrow0 = 0.f, lrow1 = 0.f;
    const int myM = wid * 16;

    for (int kt = 0; kt < S_ALL / 64; kt++) {
        if (kt + 1 < S_ALL / 64) { pref_kv(kt + 1, (kt + 1) & 1); CP_COMMIT(); CP_WAIT1(); }
        else                     { CP_WAIT0(); }
        __syncthreads();
        const uint32_t st = sKV + (kt & 1) * FSTG;

        float sacc[8][4];
#pragma unroll
        for (int j = 0; j < 8; j++)
#pragma unroll
            for (int q = 0; q < 4; q++) sacc[j][q] = 0.f;

        // S = Q K^T (3-term)
#pragma unroll
        for (int ks = 0; ks < 8; ks++) {
            uint32_t ah[4], al[4];
            uint32_t qa = (myM + (lane & 15)) * 272 + ks*32 + (lane >> 4) * 16;
            ldsm4(ah, sQh + qa);
            ldsm4(al, sQl + qa);
#pragma unroll
            for (int p = 0; p < 4; p++) {
                uint32_t ro = (16*p + (lane & 7) + (((lane >> 3) > 1) ? 8 : 0)) * 272
                            + ks*32 + ((lane >> 3) & 1) * 16;
                uint32_t bh4[4], bl4[4];
                ldsm4(bh4, st + ro);
                ldsm4(bl4, st + FKMAT + ro);
                mmabf(sacc[2*p],   ah, bh4);  mmabf(sacc[2*p+1], ah, bh4 + 2);
                mmabf(sacc[2*p],   ah, bl4);  mmabf(sacc[2*p+1], ah, bl4 + 2);
                mmabf(sacc[2*p],   al, bh4);  mmabf(sacc[2*p+1], al, bh4 + 2);
            }
        }

        // online softmax (rows r0 = lane>>2, r1 = +8; quad = lanes sharing a row)
        float mx0 = -1e30f, mx1 = -1e30f;
#pragma unroll
        for (int j = 0; j < 8; j++) {
            mx0 = fmaxf(mx0, fmaxf(sacc[j][0], sacc[j][1]));
            mx1 = fmaxf(mx1, fmaxf(sacc[j][2], sacc[j][3]));
        }
        mx0 = fmaxf(mx0, __shfl_xor_sync(0xffffffffu, mx0, 1));
        mx0 = fmaxf(mx0, __shfl_xor_sync(0xffffffffu, mx0, 2));
        mx1 = fmaxf(mx1, __shfl_xor_sync(0xffffffffu, mx1, 1));
        mx1 = fmaxf(mx1, __shfl_xor_sync(0xffffffffu, mx1, 2));
        float mn0 = fmaxf(mrow0, mx0), mn1 = fmaxf(mrow1, mx1);
        float cor0 = fexp(mrow0 - mn0), cor1 = fexp(mrow1 - mn1);
        mrow0 = mn0; mrow1 = mn1;
        float ps0 = 0.f, ps1 = 0.f;
#pragma unroll
        for (int j = 0; j < 8; j++) {
            sacc[j][0] = fexp(sacc[j][0] - mn0);
            sacc[j][1] = fexp(sacc[j][1] - mn0);
            sacc[j][2] = fexp(sacc[j][2] - mn1);
            sacc[j][3] = fexp(sacc[j][3] - mn1);
            ps0 += sacc[j][0] + sacc[j][1];
            ps1 += sacc[j][2] + sacc[j][3];
        }
        lrow0 = lrow0 * cor0 + ps0;
        lrow1 = lrow1 * cor1 + ps1;
#pragma unroll
        for (int j = 0; j < 16; j++) {
            oacc[j][0] *= cor0; oacc[j][1] *= cor0;
            oacc[j][2] *= cor1; oacc[j][3] *= cor1;
        }

        // O += P V (3-term); P A-frags repacked from S accumulators
#pragma unroll
        for (int s4 = 0; s4 < 4; s4++) {
            const float* t0 = sacc[2*s4];
            const float* t1 = sacc[2*s4 + 1];
            uint32_t aph[4], apl[4];
            aph[0] = pack2(t0[0], t0[1]); aph[1] = pack2(t0[2], t0[3]);
            aph[2] = pack2(t1[0], t1[1]); aph[3] = pack2(t1[2], t1[3]);
            {
                __nv_bfloat162 b0 = *reinterpret_cast<__nv_bfloat162*>(&aph[0]);
                __nv_bfloat162 b1 = *reinterpret_cast<__nv_bfloat162*>(&aph[1]);
                __nv_bfloat162 b2 = *reinterpret_cast<__nv_bfloat162*>(&aph[2]);
                __nv_bfloat162 b3 = *reinterpret_cast<__nv_bfloat162*>(&aph[3]);
                apl[0] = pack2(t0[0] - __bfloat162float(b0.x), t0[1] - __bfloat162float(b0.y));
                apl[1] = pack2(t0[2] - __bfloat162float(b1.x), t0[3] - __bfloat162float(b1.y));
                apl[2] = pack2(t1[0] - __bfloat162float(b2.x), t1[1] - __bfloat162float(b2.y));
                apl[3] = pack2(t1[2] - __bfloat162float(b3.x), t1[3] - __bfloat162float(b3.y));
            }
#pragma unroll
            for (int p = 0; p < 8; p++) {
                uint32_t ro = (s4*16 + (lane & 7) + ((lane >> 3) & 1) * 8) * 272
                            + p*32 + (((lane >> 3) > 1) ? 16 : 0);
                uint32_t bh4[4], bl4[4];
                ldsm4t(bh4, st + 2*FKMAT + ro);
                ldsm4t(bl4, st + 3*FKMAT + ro);
                mmabf(oacc[2*p],   aph, bh4);  mmabf(oacc[2*p+1], aph, bh4 + 2);
                mmabf(oacc[2*p],   aph, bl4);  mmabf(oacc[2*p+1], aph, bl4 + 2);
                mmabf(oacc[2*p],   apl, bh4);  mmabf(oacc[2*p+1], apl, bh4 + 2);
            }
        }
        __syncthreads();
    }

    lrow0 += __shfl_xor_sync(0xffffffffu, lrow0, 1);
    lrow0 += __shfl_xor_sync(0xffffffffu, lrow0, 2);
    lrow1 += __shfl_xor_sync(0xffffffffu, lrow1, 1);
    lrow1 += __shfl_xor_sync(0xffffffffu, lrow1, 2);
    float inv0 = 1.0f / lrow0, inv1 = 1.0f / lrow1;
    int r0 = q0 + myM + (lane >> 2), r1 = r0 + 8;
#pragma unroll
    for (int j = 0; j < 16; j++) {
        int col = h * HD + 8*j + (lane & 3) * 2;
        float f0 = oacc[j][0] * inv0, f1 = oacc[j][1] * inv0;
        float f2 = oacc[j][2] * inv1, f3 = oacc[j][3] * inv1;
        __nv_bfloat162 h0 = __floats2bfloat162_rn(f0, f1);
        __nv_bfloat162 h1 = __floats2bfloat162_rn(f2, f3);
        __nv_bfloat162 l0 = __floats2bfloat162_rn(f0 - __bfloat162float(h0.x), f1 - __bfloat162float(h0.y));
        __nv_bfloat162 l1 = __floats2bfloat162_rn(f2 - __bfloat162float(h1.x), f3 - __bfloat162float(h1.y));
        *(__nv_bfloat162*)(Oh + (size_t)r0 * DM + col) = h0;
        *(__nv_bfloat162*)(Ol + (size_t)r0 * DM + col) = l0;
        *(__nv_bfloat162*)(Oh + (size_t)r1 * DM + col) = h1;
        *(__nv_bfloat162*)(Ol + (size_t)r1 * DM + col) = l1;
    }
}

// ---------------------------------------------------------------------------
extern "C" void kernel_launch(void* const* d_in, const int* in_sizes, int n_in,
                              void* d_out, int out_size)
{
    const float* hidden  = (const float*)d_in[0];
    const float* encoder = (const float*)d_in[1];
    const float* rope    = (const float*)d_in[2];
    const float* Wq  = (const float*)d_in[3];  const float* bq  = (const float*)d_in[4];
    const float* Wk  = (const float*)d_in[5];  const float* bk  = (const float*)d_in[6];
    const float* Wv  = (const float*)d_in[7];  const float* bv  = (const float*)d_in[8];
    const float* aWq = (const float*)d_in[9];  const float* abq = (const float*)d_in[10];
    const float* aWk = (const float*)d_in[11]; const float* abk = (const float*)d_in[12];
    const float* aWv = (const float*)d_in[13]; const float* abv = (const float*)d_in[14];
    const float* nq  = (const float*)d_in[15]; const float* nk  = (const float*)d_in[16];
    const float* anq = (const float*)d_in[17]; const float* ank = (const float*)d_in[18];
    const float* Wout  = (const float*)d_in[19]; const float* bout  = (const float*)d_in[20];
    const float* Waout = (const float*)d_in[21]; const float* baout = (const float*)d_in[22];
    float* out = (float*)d_out;

    float *Qb, *Kb, *Vb;
    cudaGetSymbolAddress((void**)&Qb, g_Q);
    cudaGetSymbolAddress((void**)&Kb, g_K);
    cudaGetSymbolAddress((void**)&Vb, g_V);
    __nv_bfloat16 *hidh,*hidl,*ench,*encl,*Qhp,*Qlp,*Khp,*Klp,*Vhp,*Vlp,*Ohp,*Olp;
    cudaGetSymbolAddress((void**)&hidh, g_hid_h); cudaGetSymbolAddress((void**)&hidl, g_hid_l);
    cudaGetSymbolAddress((void**)&ench, g_enc_h); cudaGetSymbolAddress((void**)&encl, g_enc_l);
    cudaGetSymbolAddress((void**)&Qhp, g_Qh); cudaGetSymbolAddress((void**)&Qlp, g_Ql);
    cudaGetSymbolAddress((void**)&Khp, g_Kh); cudaGetSymbolAddress((void**)&Klp, g_Kl);
    cudaGetSymbolAddress((void**)&Vhp, g_Vh); cudaGetSymbolAddress((void**)&Vlp, g_Vl);
    cudaGetSymbolAddress((void**)&Ohp, g_Oh); cudaGetSymbolAddress((void**)&Olp, g_Ol);
    __nv_bfloat16 *WqTh,*WqTl,*WkTh,*WkTl,*WvTh,*WvTl,*aWqTh,*aWqTl,*aWkTh,*aWkTl,*aWvTh,*aWvTl,*WoTh,*WoTl,*WaoTh,*WaoTl;
    cudaGetSymbolAddress((void**)&WqTh,  g_WqT_h);  cudaGetSymbolAddress((void**)&WqTl,  g_WqT_l);
    cudaGetSymbolAddress((void**)&WkTh,  g_WkT_h);  cudaGetSymbolAddress((void**)&WkTl,  g_WkT_l);
    cudaGetSymbolAddress((void**)&WvTh,  g_WvT_h);  cudaGetSymbolAddress((void**)&WvTl,  g_WvT_l);
    cudaGetSymbolAddress((void**)&aWqTh, g_aWqT_h); cudaGetSymbolAddress((void**)&aWqTl, g_aWqT_l);
    cudaGetSymbolAddress((void**)&aWkTh, g_aWkT_h); cudaGetSymbolAddress((void**)&aWkTl, g_aWkT_l);
    cudaGetSymbolAddress((void**)&aWvTh, g_aWvT_h); cudaGetSymbolAddress((void**)&aWvTl, g_aWvT_l);
    cudaGetSymbolAddress((void**)&WoTh,  g_WoT_h);  cudaGetSymbolAddress((void**)&WoTl,  g_WoT_l);
    cudaGetSymbolAddress((void**)&WaoTh, g_WaoT_h); cudaGetSymbolAddress((void**)&WaoTl, g_WaoT_l);

    cudaFuncSetAttribute(tgemm_kernel,    cudaFuncAttributeMaxDynamicSharedMemorySize, GSMEM);
    cudaFuncSetAttribute(flashmma_kernel, cudaFuncAttributeMaxDynamicSharedMemorySize, F_SMEM);

    dim3 tb(32, 8);
    transpose_split_kernel<<<dim3(DM/32,   DM/32), tb>>>(Wq,    WqTh,  WqTl,  DM, DM);
    transpose_split_kernel<<<dim3(KV_W/32, DM/32), tb>>>(Wk,    WkTh,  WkTl,  DM, KV_W);
    transpose_split_kernel<<<dim3(KV_W/32, DM/32), tb>>>(Wv,    WvTh,  WvTl,  DM, KV_W);
    transpose_split_kernel<<<dim3(DM/32,   DM/32), tb>>>(aWq,   aWqTh, aWqTl, DM, DM);
    transpose_split_kernel<<<dim3(KV_W/32, DM/32), tb>>>(aWk,   aWkTh, aWkTl, DM, KV_W);
    transpose_split_kernel<<<dim3(KV_W/32, DM/32), tb>>>(aWv,   aWvTh, aWvTl, DM, KV_W);
    transpose_split_kernel<<<dim3(DM/32,   DM/32), tb>>>(Wout,  WoTh,  WoTl,  DM, DM);
    transpose_split_kernel<<<dim3(DM/32,   DM/32), tb>>>(Waout, WaoTh, WaoTl, DM, DM);
    split_kernel<<<(4096*DM/4 + 255)/256, 256>>>(hidden,  hidh, hidl, 4096*DM/4);
    split_kernel<<<(512*DM/4  + 255)/256, 256>>>(encoder, ench, encl, 512*DM/4);

    // QKV projections (f32 outputs; image rows at offset S_TXT, text at 0)
    tgemm_kernel<<<dim3(DM/128,   32), 256, GSMEM>>>(hidh, hidl, WqTh,  WqTl,  bq,  Qb + (size_t)S_TXT*DM,   DM,   DM);
    tgemm_kernel<<<dim3(DM/128,   4),  256, GSMEM>>>(ench, encl, aWqTh, aWqTl, abq, Qb,                      DM,   DM);
    tgemm_kernel<<<dim3(KV_W/128, 32), 256, GSMEM>>>(hidh, hidl, WkTh,  WkTl,  bk,  Kb + (size_t)S_TXT*KV_W, KV_W, DM);
    tgemm_kernel<<<dim3(KV_W/128, 4),  256, GSMEM>>>(ench, encl, aWkTh, aWkTl, abk, Kb,                      KV_W, DM);
    tgemm_kernel<<<dim3(KV_W/128, 32), 256, GSMEM>>>(hidh, hidl, WvTh,  WvTl,  bv,  Vb + (size_t)S_TXT*KV_W, KV_W, DM);
    tgemm_kernel<<<dim3(KV_W/128, 4),  256, GSMEM>>>(ench, encl, aWvTh, aWvTl, abv, Vb,                      KV_W, DM);

    // RMSNorm + RoPE -> bf16 hi/lo (Q absorbs 1/sqrt(HD)); V plain split
    normrope_split_kernel<<<(S_ALL*NH)/8,  256>>>(Qb, NH,  nq, anq, rope, 0.08838834764831845f, Qhp, Qlp);
    normrope_split_kernel<<<(S_ALL*NKV)/8, 256>>>(Kb, NKV, nk, ank, rope, 1.0f,                 Khp, Klp);
    split_kernel<<<(S_ALL*KV_W/4 + 255)/256, 256>>>(Vb, Vhp, Vlp, S_ALL*KV_W/4);

    // Flash attention (tensor cores), writes bf16 hi/lo O directly
    flashmma_kernel<<<dim3(S_ALL/128, NH), 256, F_SMEM>>>(Qhp, Qlp, Khp, Klp, Vhp, Vlp, Ohp, Olp);

    // Output projections: hid = O[512:] @ Wout + bout ; enc = O[:512] @ Waout + baout
    tgemm_kernel<<<dim3(DM/128, 32), 256, GSMEM>>>(Ohp + (size_t)S_TXT*DM, Olp + (size_t)S_TXT*DM, WoTh,  WoTl,  bout,  out,                   DM, DM);
    tgemm_kernel<<<dim3(DM/128, 4),  256, GSMEM>>>(Ohp,                    Olp,                    WaoTh, WaoTl, baout, out + (size_t)4096*DM, DM, DM);
}